// round 14
// baseline (speedup 1.0000x reference)
#include <cuda_runtime.h>
#include <cuda_fp16.h>
#include <math.h>

// Problem constants (fixed shapes for this problem)
#define NATOMS 50000
#define NB     10000
#define NE     320000
#define MAXE   256
#define DD     32
#define DELTA  (5.0f / 31.0f)
#define GCOEFF (-0.5f / (DELTA * DELTA))
#define DCUT   6.0f

typedef unsigned long long ull;

// ------------------------- scratch (device globals; no allocs allowed) ----
__device__ float g_Wfq[256 * 128];            // (folded Wab) @ Wq
__device__ float g_bfq[128];
__device__ float g_Wo1[128 * 128];            // Wout @ Wt1
__device__ float g_bo1[128];
__device__ float g_S[NB * 256];               // [fi+fl | fj+fk]
__device__ float g_q[NB * 128];
__device__ float g_rbpos[NB * 3];
__device__ __half g_katom[NATOMS * 128];      // fp16 k (atom part, incl. bk)
__device__ __half g_vatom[NATOMS * 128];      // fp16 v (atom part, incl. bv)
__device__ float g_C[NB * 256];               // per-bond q·Wk_bot coefs [b][j][h]
__device__ float g_msg[NB * 128];
__device__ int   g_cnt[NB];
__device__ int   g_off[NB + 1];
__device__ int   g_cur[NB];
__device__ int   g_eidx[NE];
__device__ int   g_src[NE];                   // sorted edge src atoms
__device__ float g_dist[NE];                  // sorted edge distances

// ------------------------- f32x2 packed-FMA helpers -----------------------
__device__ __forceinline__ ull pack2(float x, float y) {
    ull r;
    asm("mov.b64 %0, {%1, %2};" : "=l"(r) : "f"(x), "f"(y));
    return r;
}
__device__ __forceinline__ void unpack2(ull v, float& lo, float& hi) {
    asm("mov.b64 {%0, %1}, %2;" : "=f"(lo), "=f"(hi) : "l"(v));
}
__device__ __forceinline__ void fma2(ull& d, ull a, ull b) {
    asm("fma.rn.f32x2 %0, %1, %2, %0;" : "+l"(d) : "l"(a), "l"(b));
}

// ------------------------- gather_S (stream 0, early) ----------------------
__global__ __launch_bounds__(256) void gather_S_kernel(const float* __restrict__ feats,
                                                       const int* __restrict__ tt) {
    int idx = blockIdx.x * 256 + threadIdx.x;    // < NB*128
    int b = idx >> 7, c = idx & 127;
    int ai = tt[b * 4 + 0], aj = tt[b * 4 + 1], ak = tt[b * 4 + 2], al = tt[b * 4 + 3];
    g_S[(size_t)b * 256 + c]       = feats[(size_t)ai * 128 + c] + feats[(size_t)al * 128 + c];
    g_S[(size_t)b * 256 + 128 + c] = feats[(size_t)aj * 128 + c] + feats[(size_t)ak * 128 + c];
}

// ----------------- weight GEMMs + bias fusion (stream B, tiny) -------------
// blocks [0,8): Wfq = fold(W_dih)@Wq ; [8,12): Wo1 = Wout@Wt1 ; 12: biases.
__global__ __launch_bounds__(256) void prepw_kernel(const float* __restrict__ Wd,
                                                    const float* __restrict__ Wq,
                                                    const float* __restrict__ Wout,
                                                    const float* __restrict__ Wt1,
                                                    const float* __restrict__ b_dih,
                                                    const float* __restrict__ bq,
                                                    const float* __restrict__ bout,
                                                    const float* __restrict__ bt1) {
    const int tid = threadIdx.x;
    if (blockIdx.x == 12) {
        if (tid < 128) {
            float s1 = 0.f, s2 = 0.f;
            for (int k = 0; k < 128; k++) {
                s1 += b_dih[k] * Wq[k * 128 + tid];
                s2 += bout[k] * Wt1[k * 128 + tid];
            }
            g_bfq[tid] = bq[tid] + 2.f * s1;
            g_bo1[tid] = bt1[tid] + s2;
        }
        return;
    }
    __shared__ float As[32][33];
    __shared__ float Ws[32][128];
    const bool isFq = blockIdx.x < 8;
    const int m0 = isFq ? blockIdx.x * 32 : (blockIdx.x - 8) * 32;
    const float* W = isFq ? Wq : Wt1;
    float* C = isFq ? g_Wfq : g_Wo1;
    const int tx = tid & 15;
    const int ty = tid >> 4;

    ull acc[2][4];
#pragma unroll
    for (int r = 0; r < 2; r++)
#pragma unroll
        for (int j = 0; j < 4; j++) acc[r][j] = 0ull;

    for (int kc = 0; kc < 128; kc += 32) {
        {
            int row = tid >> 3;
            int c4 = tid & 7;
            int gr = m0 + row;
            float4 v;
            if (isFq) {
                int o = (gr < 128) ? (gr + 384) : (gr + 128);
                float4 a = *(const float4*)(Wd + (size_t)gr * 128 + kc + c4 * 4);
                float4 b = *(const float4*)(Wd + (size_t)o * 128 + kc + c4 * 4);
                v = make_float4(a.x + b.x, a.y + b.y, a.z + b.z, a.w + b.w);
            } else {
                v = *(const float4*)(Wout + (size_t)gr * 128 + kc + c4 * 4);
            }
            As[c4 * 4 + 0][row] = v.x;
            As[c4 * 4 + 1][row] = v.y;
            As[c4 * 4 + 2][row] = v.z;
            As[c4 * 4 + 3][row] = v.w;
        }
#pragma unroll
        for (int it = 0; it < 4; it++) {
            int lin = tid + 256 * it;
            int row = lin >> 5;
            int c4 = lin & 31;
            *(float4*)&Ws[row][c4 * 4] =
                *(const float4*)(W + (size_t)(kc + row) * 128 + c4 * 4);
        }
        __syncthreads();
#pragma unroll
        for (int k = 0; k < 32; k++) {
            float a0 = As[k][ty * 2 + 0], a1 = As[k][ty * 2 + 1];
            ull pa0 = pack2(a0, a0), pa1 = pack2(a1, a1);
            const ull* wp = (const ull*)&Ws[k][tx * 8];
            ull w0 = wp[0], w1 = wp[1], w2 = wp[2], w3 = wp[3];
            fma2(acc[0][0], pa0, w0); fma2(acc[0][1], pa0, w1);
            fma2(acc[0][2], pa0, w2); fma2(acc[0][3], pa0, w3);
            fma2(acc[1][0], pa1, w0); fma2(acc[1][1], pa1, w1);
            fma2(acc[1][2], pa1, w2); fma2(acc[1][3], pa1, w3);
        }
        __syncthreads();
    }
#pragma unroll
    for (int r = 0; r < 2; r++) {
        int gr = m0 + ty * 2 + r;
#pragma unroll
        for (int j = 0; j < 4; j++) {
            float lo, hi;
            unpack2(acc[r][j], lo, hi);
            *(float2*)(C + (size_t)gr * 128 + tx * 8 + j * 2) = make_float2(lo, hi);
        }
    }
}

// ------------------- rbpos + histogram (stream A) ---------------------------
// blocks [0,40): rbpos ; [40,1290): hist.
__global__ __launch_bounds__(256) void rb_hist_kernel(const int* __restrict__ rbi,
                                                      const float* __restrict__ coords,
                                                      const int* __restrict__ etgt) {
    int bid = blockIdx.x;
    int tid = threadIdx.x;
    if (bid < 40) {
        int b = bid * 256 + tid;
        if (b < NB) {
            int a0 = rbi[b], a1 = rbi[NB + b];
#pragma unroll
            for (int i = 0; i < 3; i++)
                g_rbpos[b * 3 + i] = 0.5f * (coords[(size_t)a0 * 3 + i] + coords[(size_t)a1 * 3 + i]);
        }
    } else {
        int e = (bid - 40) * 256 + tid;
        if (e < NE) atomicAdd(&g_cnt[etgt[e]], 1);
    }
}

// ------------------------- counting-sort pipeline -------------------------
__global__ __launch_bounds__(1024) void scan_kernel() {
    __shared__ int sm[1024];
    int t = threadIdx.x;
    const int CH = 10;
    int base = t * CH;
    int loc[CH];
    int tot = 0;
#pragma unroll
    for (int i = 0; i < CH; i++) {
        int v = (base + i < NB) ? g_cnt[base + i] : 0;
        loc[i] = tot;
        tot += v;
    }
    sm[t] = tot;
    __syncthreads();
    for (int off = 1; off < 1024; off <<= 1) {
        int v = (t >= off) ? sm[t - off] : 0;
        __syncthreads();
        sm[t] += v;
        __syncthreads();
    }
    int excl = sm[t] - tot;
#pragma unroll
    for (int i = 0; i < CH; i++) {
        if (base + i < NB) {
            int o = excl + loc[i];
            g_off[base + i] = o;
            g_cur[base + i] = o;
        }
    }
    if (t == 1023) g_off[NB] = sm[1023];
}

__global__ void scatter_kernel(const int* __restrict__ etgt) {
    int e = blockIdx.x * blockDim.x + threadIdx.x;
    if (e < NE) {
        int p = atomicAdd(&g_cur[etgt[e]], 1);
        g_eidx[p] = e;
    }
}

// sort each bond's edge list (determinism), then emit src + dist per slot.
__global__ __launch_bounds__(256) void sortify_kernel(const int* __restrict__ esrc,
                                                      const float* __restrict__ coords) {
    __shared__ int buf[8][MAXE];
    int warp = threadIdx.x >> 5, lane = threadIdx.x & 31;
    int b = blockIdx.x * 8 + warp;
    if (b >= NB) return;
    int s = g_off[b], e = g_off[b + 1];
    int n = e - s;
    if (n <= 0) return;
    if (n <= MAXE) {
        for (int i = lane; i < n; i += 32) buf[warp][i] = g_eidx[s + i];
        __syncwarp();
        for (int i = lane; i < n; i += 32) {
            int v = buf[warp][i];
            int r = 0;
            for (int j = 0; j < n; j++) r += (buf[warp][j] < v);
            g_eidx[s + r] = v;
        }
        __syncwarp();
    } else {
        if (lane == 0) {
            for (int i = s + 1; i < e; i++) {
                int key = g_eidx[i];
                int j = i - 1;
                while (j >= s && g_eidx[j] > key) { g_eidx[j + 1] = g_eidx[j]; j--; }
                g_eidx[j + 1] = key;
            }
        }
        __syncwarp();
    }
    float rx = g_rbpos[b * 3 + 0];
    float ry = g_rbpos[b * 3 + 1];
    float rz = g_rbpos[b * 3 + 2];
    for (int i = lane; i < n; i += 32) {
        int ed = g_eidx[s + i];
        int src = esrc[ed];
        g_src[s + i] = src;
        float dx = coords[(size_t)src * 3 + 0] - rx;
        float dy = coords[(size_t)src * 3 + 1] - ry;
        float dz = coords[(size_t)src * 3 + 2] - rz;
        g_dist[s + i] = sqrtf(dx * dx + dy * dy + dz * dz);
    }
}

// ---------------- big GEMM launch: dual k/v (blocks < DUALB) + q ----------
#define DUALB 782
#define QB    157

__global__ __launch_bounds__(256) void gemm_big(const float* __restrict__ atom_feats,
                                                const float* __restrict__ Wk,
                                                const float* __restrict__ bk,
                                                const float* __restrict__ Wv,
                                                const float* __restrict__ bv) {
    __shared__ float As[32][65];
    __shared__ float Ws[2][32][128];
    const int tid = threadIdx.x;
    const int tx = tid & 15;
    const int ty = tid >> 4;

    if (blockIdx.x < DUALB) {
        const int m0 = blockIdx.x * 64;
        ull acc[2][4][4];
#pragma unroll
        for (int p = 0; p < 2; p++)
#pragma unroll
            for (int r = 0; r < 4; r++)
#pragma unroll
                for (int j = 0; j < 4; j++) acc[p][r][j] = 0ull;

        for (int kc = 0; kc < 128; kc += 32) {
#pragma unroll
            for (int it = 0; it < 2; it++) {
                int lin = tid + 256 * it;
                int row = lin >> 3;
                int c4 = lin & 7;
                float4 v = make_float4(0.f, 0.f, 0.f, 0.f);
                int gr = m0 + row;
                if (gr < NATOMS) v = *(const float4*)(atom_feats + (size_t)gr * 128 + kc + c4 * 4);
                As[c4 * 4 + 0][row] = v.x;
                As[c4 * 4 + 1][row] = v.y;
                As[c4 * 4 + 2][row] = v.z;
                As[c4 * 4 + 3][row] = v.w;
            }
#pragma unroll
            for (int it = 0; it < 4; it++) {
                int lin = tid + 256 * it;
                int row = lin >> 5;
                int c4 = lin & 31;
                *(float4*)&Ws[0][row][c4 * 4] =
                    *(const float4*)(Wk + (size_t)(kc + row) * 128 + c4 * 4);
                *(float4*)&Ws[1][row][c4 * 4] =
                    *(const float4*)(Wv + (size_t)(kc + row) * 128 + c4 * 4);
            }
            __syncthreads();
#pragma unroll
            for (int k = 0; k < 32; k++) {
                float a0 = As[k][ty * 4 + 0], a1 = As[k][ty * 4 + 1];
                float a2 = As[k][ty * 4 + 2], a3 = As[k][ty * 4 + 3];
                ull pa0 = pack2(a0, a0), pa1 = pack2(a1, a1);
                ull pa2 = pack2(a2, a2), pa3 = pack2(a3, a3);
#pragma unroll
                for (int p = 0; p < 2; p++) {
                    const ull* wp = (const ull*)&Ws[p][k][tx * 8];
                    ull w0 = wp[0], w1 = wp[1], w2 = wp[2], w3 = wp[3];
                    fma2(acc[p][0][0], pa0, w0); fma2(acc[p][0][1], pa0, w1);
                    fma2(acc[p][0][2], pa0, w2); fma2(acc[p][0][3], pa0, w3);
                    fma2(acc[p][1][0], pa1, w0); fma2(acc[p][1][1], pa1, w1);
                    fma2(acc[p][1][2], pa1, w2); fma2(acc[p][1][3], pa1, w3);
                    fma2(acc[p][2][0], pa2, w0); fma2(acc[p][2][1], pa2, w1);
                    fma2(acc[p][2][2], pa2, w2); fma2(acc[p][2][3], pa2, w3);
                    fma2(acc[p][3][0], pa3, w0); fma2(acc[p][3][1], pa3, w1);
                    fma2(acc[p][3][2], pa3, w2); fma2(acc[p][3][3], pa3, w3);
                }
            }
            __syncthreads();
        }
#pragma unroll
        for (int p = 0; p < 2; p++) {
            const float* bias = p ? bv : bk;
            __half* C = p ? g_vatom : g_katom;
            float bb[8];
#pragma unroll
            for (int j = 0; j < 8; j++) bb[j] = bias[tx * 8 + j];
#pragma unroll
            for (int r = 0; r < 4; r++) {
                int gr = m0 + ty * 4 + r;
                if (gr >= NATOMS) continue;
#pragma unroll
                for (int j = 0; j < 4; j++) {
                    float lo, hi;
                    unpack2(acc[p][r][j], lo, hi);
                    *(__half2*)(C + (size_t)gr * 128 + tx * 8 + j * 2) =
                        __floats2half2_rn(lo + bb[j * 2], hi + bb[j * 2 + 1]);
                }
            }
        }
    } else {
        // q = S @ Wfq + bfq   (K = 256)
        const int m0 = (blockIdx.x - DUALB) * 64;
        ull acc[4][4];
#pragma unroll
        for (int r = 0; r < 4; r++)
#pragma unroll
            for (int j = 0; j < 4; j++) acc[r][j] = 0ull;

        for (int kc = 0; kc < 256; kc += 32) {
#pragma unroll
            for (int it = 0; it < 2; it++) {
                int lin = tid + 256 * it;
                int row = lin >> 3;
                int c4 = lin & 7;
                float4 v = make_float4(0.f, 0.f, 0.f, 0.f);
                int gr = m0 + row;
                if (gr < NB) v = *(const float4*)(g_S + (size_t)gr * 256 + kc + c4 * 4);
                As[c4 * 4 + 0][row] = v.x;
                As[c4 * 4 + 1][row] = v.y;
                As[c4 * 4 + 2][row] = v.z;
                As[c4 * 4 + 3][row] = v.w;
            }
#pragma unroll
            for (int it = 0; it < 4; it++) {
                int lin = tid + 256 * it;
                int row = lin >> 5;
                int c4 = lin & 31;
                *(float4*)&Ws[0][row][c4 * 4] =
                    *(const float4*)(g_Wfq + (size_t)(kc + row) * 128 + c4 * 4);
            }
            __syncthreads();
#pragma unroll
            for (int k = 0; k < 32; k++) {
                float a0 = As[k][ty * 4 + 0], a1 = As[k][ty * 4 + 1];
                float a2 = As[k][ty * 4 + 2], a3 = As[k][ty * 4 + 3];
                ull pa0 = pack2(a0, a0), pa1 = pack2(a1, a1);
                ull pa2 = pack2(a2, a2), pa3 = pack2(a3, a3);
                const ull* wp = (const ull*)&Ws[0][k][tx * 8];
                ull w0 = wp[0], w1 = wp[1], w2 = wp[2], w3 = wp[3];
                fma2(acc[0][0], pa0, w0); fma2(acc[0][1], pa0, w1);
                fma2(acc[0][2], pa0, w2); fma2(acc[0][3], pa0, w3);
                fma2(acc[1][0], pa1, w0); fma2(acc[1][1], pa1, w1);
                fma2(acc[1][2], pa1, w2); fma2(acc[1][3], pa1, w3);
                fma2(acc[2][0], pa2, w0); fma2(acc[2][1], pa2, w1);
                fma2(acc[2][2], pa2, w2); fma2(acc[2][3], pa2, w3);
                fma2(acc[3][0], pa3, w0); fma2(acc[3][1], pa3, w1);
                fma2(acc[3][2], pa3, w2); fma2(acc[3][3], pa3, w3);
            }
            __syncthreads();
        }
        float bb[8];
#pragma unroll
        for (int j = 0; j < 8; j++) bb[j] = g_bfq[tx * 8 + j];
#pragma unroll
        for (int r = 0; r < 4; r++) {
            int gr = m0 + ty * 4 + r;
            if (gr >= NB) continue;
#pragma unroll
            for (int j = 0; j < 4; j++) {
                float lo, hi;
                unpack2(acc[r][j], lo, hi);
                *(float2*)(g_q + (size_t)gr * 128 + tx * 8 + j * 2) =
                    make_float2(lo + bb[j * 2], hi + bb[j * 2 + 1]);
            }
        }
    }
}

// --------- per-bond gaussian-basis logit coefs: C[b][j][h] ----------------
// shuffle-free: lane owns (h = l>>2, j = (l&3)+4*jj); q in registers,
// Wk_bot via __ldg float4 (L1-hot across the 8 bonds per block).
__global__ __launch_bounds__(256) void qkcoef_kernel(const float* __restrict__ Wk) {
    int tid = threadIdx.x;
    int w = tid >> 5, l = tid & 31;
    int b = blockIdx.x * 8 + w;
    if (b >= NB) return;
    int h = l >> 2;
    int jg = l & 3;
    const float4* qp = (const float4*)&g_q[(size_t)b * 128 + h * 16];
    float4 q0 = qp[0], q1 = qp[1], q2 = qp[2], q3 = qp[3];
#pragma unroll
    for (int jj = 0; jj < 8; jj++) {
        int j = jg + 4 * jj;
        const float4* wp = (const float4*)&Wk[(size_t)(128 + j) * 128 + h * 16];
        float4 w0 = __ldg(wp + 0);
        float4 w1 = __ldg(wp + 1);
        float4 w2 = __ldg(wp + 2);
        float4 w3 = __ldg(wp + 3);
        float sum = q0.x * w0.x + q0.y * w0.y + q0.z * w0.z + q0.w * w0.w
                  + q1.x * w1.x + q1.y * w1.y + q1.z * w1.z + q1.w * w1.w
                  + q2.x * w2.x + q2.y * w2.y + q2.z * w2.z + q2.w * w2.w
                  + q3.x * w3.x + q3.y * w3.y + q3.z * w3.z + q3.w * w3.w;
        g_C[(size_t)b * 256 + j * 8 + h] = sum;
    }
}

// ------------------------- attention core (vcorr fused) --------------------
__global__ __launch_bounds__(128) void attn_kernel(const float* __restrict__ Wv) {
    __shared__ float Cs[32][8];
    __shared__ float ssm[4][8];
    __shared__ float accs[4][128];
    __shared__ float sjs[4][256];
    __shared__ float sjtot[256];              // [h][j]
    __shared__ float Ssm[8];

    const int b = blockIdx.x;
    const int tid = threadIdx.x;
    const int w = tid >> 5;
    const int l = tid & 31;
    const int h = l >> 2;
    const int t = l & 3;

    ((float*)Cs)[tid] = g_C[(size_t)b * 256 + tid];
    ((float*)Cs)[tid + 128] = g_C[(size_t)b * 256 + tid + 128];
    __syncthreads();

    const float4 q4 = *(const float4*)&g_q[(size_t)b * 128 + l * 4];
    const int s0 = g_off[b], s1 = g_off[b + 1];

    float s = 0.f;
    float ax = 0.f, ay = 0.f, az = 0.f, aw = 0.f;
    float sj[8];
#pragma unroll
    for (int jj = 0; jj < 8; jj++) sj[jj] = 0.f;

    int i = s0 + w;
    float dist = 0.f;
    uint2 kraw = make_uint2(0u, 0u), vraw = make_uint2(0u, 0u);
    if (i < s1) {
        int src = g_src[i];
        dist = g_dist[i];
        kraw = *(const uint2*)&g_katom[(size_t)src * 128 + l * 4];
        vraw = *(const uint2*)&g_vatom[(size_t)src * 128 + l * 4];
    }
    while (i < s1) {
        int ni = i + 4;
        float ndist = 0.f;
        uint2 nkraw = make_uint2(0u, 0u), nvraw = make_uint2(0u, 0u);
        if (ni < s1) {
            int nsrc = g_src[ni];
            ndist = g_dist[ni];
            nkraw = *(const uint2*)&g_katom[(size_t)nsrc * 128 + l * 4];
            nvraw = *(const uint2*)&g_vatom[(size_t)nsrc * 128 + l * 4];
        }

        float2 k01 = __half22float2(*(__half2*)&kraw.x);
        float2 k23 = __half22float2(*(__half2*)&kraw.y);
        float2 v01 = __half22float2(*(__half2*)&vraw.x);
        float2 v23 = __half22float2(*(__half2*)&vraw.y);

        const bool hasg = dist < DCUT;           // warp-uniform branch
        float ev[8];
        float epart = 0.f;
        if (hasg) {
#pragma unroll
            for (int jj = 0; jj < 8; jj++) {
                int j = t + 4 * jj;
                float u = dist - (float)j * DELTA;
                float e = __expf(GCOEFF * u * u);
                ev[jj] = e;
                epart += e * Cs[j][h];
            }
        }
        float part = q4.x * k01.x + q4.y * k01.y + q4.z * k23.x + q4.w * k23.y + epart;
        part += __shfl_xor_sync(0xffffffffu, part, 1);
        part += __shfl_xor_sync(0xffffffffu, part, 2);
        float p = __expf(part * 0.25f);        // 1/sqrt(HEAD_DIM)

        s += p;
        ax += p * v01.x;
        ay += p * v01.y;
        az += p * v23.x;
        aw += p * v23.y;
        if (hasg) {
#pragma unroll
            for (int jj = 0; jj < 8; jj++) sj[jj] += p * ev[jj];
        }

        i = ni; dist = ndist; kraw = nkraw; vraw = nvraw;
    }

    if (t == 0) ssm[w][h] = s;
    accs[w][l * 4 + 0] = ax;
    accs[w][l * 4 + 1] = ay;
    accs[w][l * 4 + 2] = az;
    accs[w][l * 4 + 3] = aw;
#pragma unroll
    for (int jj = 0; jj < 8; jj++) sjs[w][l * 8 + jj] = sj[jj];
    __syncthreads();

    if (tid < 8) {
        float S = 0.f;
#pragma unroll
        for (int ww = 0; ww < 4; ww++) S += ssm[ww][tid];
        Ssm[tid] = S;
    }
    // reduce gaussian-basis accumulators into [h][j] layout
#pragma unroll
    for (int r = 0; r < 2; r++) {
        int idx = tid + 128 * r;
        int hh = idx >> 5, j = idx & 31;
        int tt2 = j & 3, jj = j >> 2;
        float v = 0.f;
#pragma unroll
        for (int ww = 0; ww < 4; ww++) v += sjs[ww][(4 * hh + tt2) * 8 + jj];
        sjtot[idx] = v;
    }
    __syncthreads();

    // fused vcorr: per-channel Wv_bot correction + normalization
    {
        const int c = tid;
        const int hh = c >> 4;
        float a = accs[0][c] + accs[1][c] + accs[2][c] + accs[3][c];
        float corr = 0.f;
        const float* sjh = &sjtot[hh * 32];
#pragma unroll
        for (int j = 0; j < 32; j++)
            corr += __ldg(&Wv[(size_t)(128 + j) * 128 + c]) * sjh[j];
        g_msg[(size_t)b * 128 + c] = (a + corr) / (Ssm[hh] + 1e-16f);
    }
}

// ------- GELU GEMM + fused final projection: out = gelu(msg@Wo1+bo1)@Wt2+bt2
__global__ __launch_bounds__(256) void gemm_gelu_t2(const float* __restrict__ Wt2,
                                                    const float* __restrict__ bt2,
                                                    float* __restrict__ out) {
    __shared__ float As[32][65];
    __shared__ float Ws[32][128];
    const int tid = threadIdx.x;
    const int tx = tid & 15;
    const int ty = tid >> 4;
    const int m0 = blockIdx.x * 64;

    ull acc[4][4];
#pragma unroll
    for (int r = 0; r < 4; r++)
#pragma unroll
        for (int j = 0; j < 4; j++) acc[r][j] = 0ull;

    for (int kc = 0; kc < 128; kc += 32) {
#pragma unroll
        for (int it = 0; it < 2; it++) {
            int lin = tid + 256 * it;
            int row = lin >> 3;
            int c4 = lin & 7;
            float4 v = make_float4(0.f, 0.f, 0.f, 0.f);
            int gr = m0 + row;
            if (gr < NB) v = *(const float4*)(g_msg + (size_t)gr * 128 + kc + c4 * 4);
            As[c4 * 4 + 0][row] = v.x;
            As[c4 * 4 + 1][row] = v.y;
            As[c4 * 4 + 2][row] = v.z;
            As[c4 * 4 + 3][row] = v.w;
        }
#pragma unroll
        for (int it = 0; it < 4; it++) {
            int lin = tid + 256 * it;
            int row = lin >> 5;
            int c4 = lin & 31;
            *(float4*)&Ws[row][c4 * 4] =
                *(const float4*)(g_Wo1 + (size_t)(kc + row) * 128 + c4 * 4);
        }
        __syncthreads();
#pragma unroll
        for (int k = 0; k < 32; k++) {
            float a0 = As[k][ty * 4 + 0], a1 = As[k][ty * 4 + 1];
            float a2 = As[k][ty * 4 + 2], a3 = As[k][ty * 4 + 3];
            ull pa0 = pack2(a0, a0), pa1 = pack2(a1, a1);
            ull pa2 = pack2(a2, a2), pa3 = pack2(a3, a3);
            const ull* wp = (const ull*)&Ws[k][tx * 8];
            ull w0 = wp[0], w1 = wp[1], w2 = wp[2], w3 = wp[3];
            fma2(acc[0][0], pa0, w0); fma2(acc[0][1], pa0, w1);
            fma2(acc[0][2], pa0, w2); fma2(acc[0][3], pa0, w3);
            fma2(acc[1][0], pa1, w0); fma2(acc[1][1], pa1, w1);
            fma2(acc[1][2], pa1, w2); fma2(acc[1][3], pa1, w3);
            fma2(acc[2][0], pa2, w0); fma2(acc[2][1], pa2, w1);
            fma2(acc[2][2], pa2, w2); fma2(acc[2][3], pa2, w3);
            fma2(acc[3][0], pa3, w0); fma2(acc[3][1], pa3, w1);
            fma2(acc[3][2], pa3, w2); fma2(acc[3][3], pa3, w3);
        }
        __syncthreads();
    }

    float bb[8];
    float wt2a[8], wt2b[8];
#pragma unroll
    for (int j = 0; j < 8; j++) {
        bb[j] = g_bo1[tx * 8 + j];
        wt2a[j] = Wt2[(tx * 8 + j) * 2 + 0];
        wt2b[j] = Wt2[(tx * 8 + j) * 2 + 1];
    }
    float bt0 = bt2[0], bt1v = bt2[1];
#pragma unroll
    for (int r = 0; r < 4; r++) {
        int gr = m0 + ty * 4 + r;
        float a0 = 0.f, a1 = 0.f;
#pragma unroll
        for (int j = 0; j < 4; j++) {
            float lo, hi;
            unpack2(acc[r][j], lo, hi);
            lo += bb[j * 2];
            hi += bb[j * 2 + 1];
            lo = 0.5f * lo * (1.f + erff(lo * 0.70710678118654752f));
            hi = 0.5f * hi * (1.f + erff(hi * 0.70710678118654752f));
            a0 += lo * wt2a[j * 2] + hi * wt2a[j * 2 + 1];
            a1 += lo * wt2b[j * 2] + hi * wt2b[j * 2 + 1];
        }
#pragma unroll
        for (int o = 8; o; o >>= 1) {
            a0 += __shfl_xor_sync(0xffffffffu, a0, o);
            a1 += __shfl_xor_sync(0xffffffffu, a1, o);
        }
        if (tx == 0 && gr < NB) {
            out[gr * 2 + 0] = a0 + bt0;
            out[gr * 2 + 1] = a1 + bt1v;
        }
    }
}

// ------------------------- launch -----------------------------------------
extern "C" void kernel_launch(void* const* d_in, const int* in_sizes, int n_in,
                              void* d_out, int out_size) {
    const float* atom_feats = (const float*)d_in[0];
    const float* coords     = (const float*)d_in[1];
    const int*   rbi        = (const int*)d_in[2];
    const int*   etgt       = (const int*)d_in[3];
    const int*   esrc       = (const int*)d_in[4];
    const int*   tt         = (const int*)d_in[5];
    const float* W_dih      = (const float*)d_in[6];
    const float* b_dih      = (const float*)d_in[7];
    const float* Wq         = (const float*)d_in[8];
    const float* bq         = (const float*)d_in[9];
    const float* Wk         = (const float*)d_in[10];
    const float* bk         = (const float*)d_in[11];
    const float* Wv         = (const float*)d_in[12];
    const float* bv         = (const float*)d_in[13];
    const float* Wout       = (const float*)d_in[14];
    const float* bout       = (const float*)d_in[15];
    const float* Wt1        = (const float*)d_in[16];
    const float* bt1        = (const float*)d_in[17];
    const float* Wt2        = (const float*)d_in[18];
    const float* bt2        = (const float*)d_in[19];
    float* out = (float*)d_out;

    static cudaStream_t s1 = []() {
        cudaStream_t s;
        cudaStreamCreateWithFlags(&s, cudaStreamNonBlocking);
        return s;
    }();
    static cudaEvent_t evFork = []() {
        cudaEvent_t e;
        cudaEventCreateWithFlags(&e, cudaEventDisableTiming);
        return e;
    }();
    static cudaEvent_t evS = []() {
        cudaEvent_t e;
        cudaEventCreateWithFlags(&e, cudaEventDisableTiming);
        return e;
    }();
    static cudaEvent_t evJoin = []() {
        cudaEvent_t e;
        cudaEventCreateWithFlags(&e, cudaEventDisableTiming);
        return e;
    }();

    void* pcnt;
    cudaGetSymbolAddress(&pcnt, g_cnt);

    // fork: stream B (s1) branches off the main stream
    cudaEventRecord(evFork, 0);
    cudaStreamWaitEvent(s1, evFork, 0);

    // ---- chain A (stream 0): gather_S first (feeds gemm_big's q branch),
    //      then the counting-sort pipeline ----
    gather_S_kernel<<<5000, 256>>>(atom_feats, tt);
    cudaEventRecord(evS, 0);
    cudaMemsetAsync(pcnt, 0, NB * sizeof(int));
    rb_hist_kernel<<<1290, 256>>>(rbi, coords, etgt);
    scan_kernel<<<1, 1024>>>();
    scatter_kernel<<<(NE + 255) / 256, 256>>>(etgt);
    sortify_kernel<<<(NB + 7) / 8, 256>>>(esrc, coords);

    // ---- chain B (s1): weight GEMMs (concurrent with gather_S),
    //      then wait for g_S, then big GEMMs -> qk coefs ----
    prepw_kernel<<<13, 256, 0, s1>>>(W_dih, Wq, Wout, Wt1, b_dih, bq, bout, bt1);
    cudaStreamWaitEvent(s1, evS, 0);
    gemm_big<<<DUALB + QB, 256, 0, s1>>>(atom_feats, Wk, bk, Wv, bv);
    qkcoef_kernel<<<(NB + 7) / 8, 256, 0, s1>>>(Wk);

    // join: main stream waits for chain B
    cudaEventRecord(evJoin, s1);
    cudaStreamWaitEvent(0, evJoin, 0);

    // ---- tail (stream 0): attn (with fused vcorr) -> gelu+t2 ----
    attn_kernel<<<NB, 128>>>(Wv);
    gemm_gelu_t2<<<(NB + 63) / 64, 256>>>(Wt2, bt2, out);

    (void)in_sizes; (void)n_in; (void)out_size;
}

// round 15
// speedup vs baseline: 1.0516x; 1.0516x over previous
#include <cuda_runtime.h>
#include <cuda_fp16.h>
#include <math.h>

// Problem constants (fixed shapes for this problem)
#define NATOMS 50000
#define NB     10000
#define NE     320000
#define MAXE   256
#define DD     32
#define DELTA  (5.0f / 31.0f)
#define GCOEFF (-0.5f / (DELTA * DELTA))
#define DCUT   6.0f

typedef unsigned long long ull;

// ------------------------- scratch (device globals; no allocs allowed) ----
__device__ float g_Wfq[256 * 128];            // (folded Wab) @ Wq
__device__ float g_bfq[128];
__device__ float g_Wo1[128 * 128];            // Wout @ Wt1
__device__ float g_bo1[128];
__device__ float g_S[NB * 256];               // [fi+fl | fj+fk]
__device__ float g_q[NB * 128];
__device__ float g_rbpos[NB * 3];
__device__ __half g_katom[NATOMS * 128];      // fp16 k (atom part, incl. bk)
__device__ __half g_vatom[NATOMS * 128];      // fp16 v (atom part, incl. bv)
__device__ float g_C[NB * 256];               // per-bond q·Wk_bot coefs [b][j][h]
__device__ float g_msg[NB * 128];
__device__ int   g_cnt[NB];
__device__ int   g_off[NB + 1];
__device__ int   g_cur[NB];
__device__ int   g_eidx[NE];
__device__ int   g_src[NE];                   // sorted edge src atoms
__device__ float g_dist[NE];                  // sorted edge distances

// ------------------------- f32x2 packed-FMA helpers -----------------------
__device__ __forceinline__ ull pack2(float x, float y) {
    ull r;
    asm("mov.b64 %0, {%1, %2};" : "=l"(r) : "f"(x), "f"(y));
    return r;
}
__device__ __forceinline__ void unpack2(ull v, float& lo, float& hi) {
    asm("mov.b64 {%0, %1}, %2;" : "=f"(lo), "=f"(hi) : "l"(v));
}
__device__ __forceinline__ void fma2(ull& d, ull a, ull b) {
    asm("fma.rn.f32x2 %0, %1, %2, %0;" : "+l"(d) : "l"(a), "l"(b));
}

// ------------------------- prep kernel (stream B) --------------------------
// blocks [0,5000): gather_S ; [5000,5012): weight GEMMs ; 5012: fused biases.
__global__ __launch_bounds__(256) void prep_kernel(const float* __restrict__ feats,
                                                   const int* __restrict__ tt,
                                                   const float* __restrict__ Wd,
                                                   const float* __restrict__ Wq,
                                                   const float* __restrict__ Wout,
                                                   const float* __restrict__ Wt1,
                                                   const float* __restrict__ b_dih,
                                                   const float* __restrict__ bq,
                                                   const float* __restrict__ bout,
                                                   const float* __restrict__ bt1) {
    __shared__ float As[32][33];
    __shared__ float Ws[32][128];
    int bid = blockIdx.x;
    int tid = threadIdx.x;
    if (bid < 5000) {
        int idx = bid * 256 + tid;               // < NB*128
        int b = idx >> 7, c = idx & 127;
        int ai = tt[b * 4 + 0], aj = tt[b * 4 + 1], ak = tt[b * 4 + 2], al = tt[b * 4 + 3];
        g_S[(size_t)b * 256 + c]       = feats[(size_t)ai * 128 + c] + feats[(size_t)al * 128 + c];
        g_S[(size_t)b * 256 + 128 + c] = feats[(size_t)aj * 128 + c] + feats[(size_t)ak * 128 + c];
        return;
    }
    if (bid == 5012) {
        if (tid < 128) {
            float s1 = 0.f, s2 = 0.f;
            for (int k = 0; k < 128; k++) {
                s1 += b_dih[k] * Wq[k * 128 + tid];
                s2 += bout[k] * Wt1[k * 128 + tid];
            }
            g_bfq[tid] = bq[tid] + 2.f * s1;
            g_bo1[tid] = bt1[tid] + s2;
        }
        return;
    }
    // weight GEMMs: Wfq = fold(W_dih)@Wq (8 blocks) ; Wo1 = Wout@Wt1 (4 blocks)
    const int wb = bid - 5000;
    const bool isFq = wb < 8;
    const int m0 = isFq ? wb * 32 : (wb - 8) * 32;
    const float* W = isFq ? Wq : Wt1;
    float* C = isFq ? g_Wfq : g_Wo1;
    const int tx = tid & 15;
    const int ty = tid >> 4;

    ull acc[2][4];
#pragma unroll
    for (int r = 0; r < 2; r++)
#pragma unroll
        for (int j = 0; j < 4; j++) acc[r][j] = 0ull;

    for (int kc = 0; kc < 128; kc += 32) {
        {
            int row = tid >> 3;
            int c4 = tid & 7;
            int gr = m0 + row;
            float4 v;
            if (isFq) {
                int o = (gr < 128) ? (gr + 384) : (gr + 128);
                float4 a = *(const float4*)(Wd + (size_t)gr * 128 + kc + c4 * 4);
                float4 b = *(const float4*)(Wd + (size_t)o * 128 + kc + c4 * 4);
                v = make_float4(a.x + b.x, a.y + b.y, a.z + b.z, a.w + b.w);
            } else {
                v = *(const float4*)(Wout + (size_t)gr * 128 + kc + c4 * 4);
            }
            As[c4 * 4 + 0][row] = v.x;
            As[c4 * 4 + 1][row] = v.y;
            As[c4 * 4 + 2][row] = v.z;
            As[c4 * 4 + 3][row] = v.w;
        }
#pragma unroll
        for (int it = 0; it < 4; it++) {
            int lin = tid + 256 * it;
            int row = lin >> 5;
            int c4 = lin & 31;
            *(float4*)&Ws[row][c4 * 4] =
                *(const float4*)(W + (size_t)(kc + row) * 128 + c4 * 4);
        }
        __syncthreads();
#pragma unroll
        for (int k = 0; k < 32; k++) {
            float a0 = As[k][ty * 2 + 0], a1 = As[k][ty * 2 + 1];
            ull pa0 = pack2(a0, a0), pa1 = pack2(a1, a1);
            const ull* wp = (const ull*)&Ws[k][tx * 8];
            ull w0 = wp[0], w1 = wp[1], w2 = wp[2], w3 = wp[3];
            fma2(acc[0][0], pa0, w0); fma2(acc[0][1], pa0, w1);
            fma2(acc[0][2], pa0, w2); fma2(acc[0][3], pa0, w3);
            fma2(acc[1][0], pa1, w0); fma2(acc[1][1], pa1, w1);
            fma2(acc[1][2], pa1, w2); fma2(acc[1][3], pa1, w3);
        }
        __syncthreads();
    }
#pragma unroll
    for (int r = 0; r < 2; r++) {
        int gr = m0 + ty * 2 + r;
#pragma unroll
        for (int j = 0; j < 4; j++) {
            float lo, hi;
            unpack2(acc[r][j], lo, hi);
            *(float2*)(C + (size_t)gr * 128 + tx * 8 + j * 2) = make_float2(lo, hi);
        }
    }
}

// ------------------- rbpos + histogram (stream A) ---------------------------
// blocks [0,40): rbpos ; [40,1290): hist.
__global__ __launch_bounds__(256) void rb_hist_kernel(const int* __restrict__ rbi,
                                                      const float* __restrict__ coords,
                                                      const int* __restrict__ etgt) {
    int bid = blockIdx.x;
    int tid = threadIdx.x;
    if (bid < 40) {
        int b = bid * 256 + tid;
        if (b < NB) {
            int a0 = rbi[b], a1 = rbi[NB + b];
#pragma unroll
            for (int i = 0; i < 3; i++)
                g_rbpos[b * 3 + i] = 0.5f * (coords[(size_t)a0 * 3 + i] + coords[(size_t)a1 * 3 + i]);
        }
    } else {
        int e = (bid - 40) * 256 + tid;
        if (e < NE) atomicAdd(&g_cnt[etgt[e]], 1);
    }
}

// ------------------------- counting-sort pipeline -------------------------
__global__ __launch_bounds__(1024) void scan_kernel() {
    __shared__ int sm[1024];
    int t = threadIdx.x;
    const int CH = 10;
    int base = t * CH;
    int loc[CH];
    int tot = 0;
#pragma unroll
    for (int i = 0; i < CH; i++) {
        int v = (base + i < NB) ? g_cnt[base + i] : 0;
        loc[i] = tot;
        tot += v;
    }
    sm[t] = tot;
    __syncthreads();
    for (int off = 1; off < 1024; off <<= 1) {
        int v = (t >= off) ? sm[t - off] : 0;
        __syncthreads();
        sm[t] += v;
        __syncthreads();
    }
    int excl = sm[t] - tot;
#pragma unroll
    for (int i = 0; i < CH; i++) {
        if (base + i < NB) {
            int o = excl + loc[i];
            g_off[base + i] = o;
            g_cur[base + i] = o;
        }
    }
    if (t == 1023) g_off[NB] = sm[1023];
}

__global__ void scatter_kernel(const int* __restrict__ etgt) {
    int e = blockIdx.x * blockDim.x + threadIdx.x;
    if (e < NE) {
        int p = atomicAdd(&g_cur[etgt[e]], 1);
        g_eidx[p] = e;
    }
}

// sort each bond's edge list (determinism), then emit src + dist per slot.
__global__ __launch_bounds__(256) void sortify_kernel(const int* __restrict__ esrc,
                                                      const float* __restrict__ coords) {
    __shared__ int buf[8][MAXE];
    int warp = threadIdx.x >> 5, lane = threadIdx.x & 31;
    int b = blockIdx.x * 8 + warp;
    if (b >= NB) return;
    int s = g_off[b], e = g_off[b + 1];
    int n = e - s;
    if (n <= 0) return;
    if (n <= MAXE) {
        for (int i = lane; i < n; i += 32) buf[warp][i] = g_eidx[s + i];
        __syncwarp();
        for (int i = lane; i < n; i += 32) {
            int v = buf[warp][i];
            int r = 0;
            for (int j = 0; j < n; j++) r += (buf[warp][j] < v);
            g_eidx[s + r] = v;
        }
        __syncwarp();
    } else {
        if (lane == 0) {
            for (int i = s + 1; i < e; i++) {
                int key = g_eidx[i];
                int j = i - 1;
                while (j >= s && g_eidx[j] > key) { g_eidx[j + 1] = g_eidx[j]; j--; }
                g_eidx[j + 1] = key;
            }
        }
        __syncwarp();
    }
    float rx = g_rbpos[b * 3 + 0];
    float ry = g_rbpos[b * 3 + 1];
    float rz = g_rbpos[b * 3 + 2];
    for (int i = lane; i < n; i += 32) {
        int ed = g_eidx[s + i];
        int src = esrc[ed];
        g_src[s + i] = src;
        float dx = coords[(size_t)src * 3 + 0] - rx;
        float dy = coords[(size_t)src * 3 + 1] - ry;
        float dz = coords[(size_t)src * 3 + 2] - rz;
        g_dist[s + i] = sqrtf(dx * dx + dy * dy + dz * dz);
    }
}

// ---------------- big GEMM launch: dual k/v (blocks < DUALB) + q ----------
#define DUALB 782
#define QB    157

__global__ __launch_bounds__(256) void gemm_big(const float* __restrict__ atom_feats,
                                                const float* __restrict__ Wk,
                                                const float* __restrict__ bk,
                                                const float* __restrict__ Wv,
                                                const float* __restrict__ bv) {
    __shared__ float As[32][65];
    __shared__ float Ws[2][32][128];
    const int tid = threadIdx.x;
    const int tx = tid & 15;
    const int ty = tid >> 4;

    if (blockIdx.x < DUALB) {
        const int m0 = blockIdx.x * 64;
        ull acc[2][4][4];
#pragma unroll
        for (int p = 0; p < 2; p++)
#pragma unroll
            for (int r = 0; r < 4; r++)
#pragma unroll
                for (int j = 0; j < 4; j++) acc[p][r][j] = 0ull;

        for (int kc = 0; kc < 128; kc += 32) {
#pragma unroll
            for (int it = 0; it < 2; it++) {
                int lin = tid + 256 * it;
                int row = lin >> 3;
                int c4 = lin & 7;
                float4 v = make_float4(0.f, 0.f, 0.f, 0.f);
                int gr = m0 + row;
                if (gr < NATOMS) v = *(const float4*)(atom_feats + (size_t)gr * 128 + kc + c4 * 4);
                As[c4 * 4 + 0][row] = v.x;
                As[c4 * 4 + 1][row] = v.y;
                As[c4 * 4 + 2][row] = v.z;
                As[c4 * 4 + 3][row] = v.w;
            }
#pragma unroll
            for (int it = 0; it < 4; it++) {
                int lin = tid + 256 * it;
                int row = lin >> 5;
                int c4 = lin & 31;
                *(float4*)&Ws[0][row][c4 * 4] =
                    *(const float4*)(Wk + (size_t)(kc + row) * 128 + c4 * 4);
                *(float4*)&Ws[1][row][c4 * 4] =
                    *(const float4*)(Wv + (size_t)(kc + row) * 128 + c4 * 4);
            }
            __syncthreads();
#pragma unroll
            for (int k = 0; k < 32; k++) {
                float a0 = As[k][ty * 4 + 0], a1 = As[k][ty * 4 + 1];
                float a2 = As[k][ty * 4 + 2], a3 = As[k][ty * 4 + 3];
                ull pa0 = pack2(a0, a0), pa1 = pack2(a1, a1);
                ull pa2 = pack2(a2, a2), pa3 = pack2(a3, a3);
#pragma unroll
                for (int p = 0; p < 2; p++) {
                    const ull* wp = (const ull*)&Ws[p][k][tx * 8];
                    ull w0 = wp[0], w1 = wp[1], w2 = wp[2], w3 = wp[3];
                    fma2(acc[p][0][0], pa0, w0); fma2(acc[p][0][1], pa0, w1);
                    fma2(acc[p][0][2], pa0, w2); fma2(acc[p][0][3], pa0, w3);
                    fma2(acc[p][1][0], pa1, w0); fma2(acc[p][1][1], pa1, w1);
                    fma2(acc[p][1][2], pa1, w2); fma2(acc[p][1][3], pa1, w3);
                    fma2(acc[p][2][0], pa2, w0); fma2(acc[p][2][1], pa2, w1);
                    fma2(acc[p][2][2], pa2, w2); fma2(acc[p][2][3], pa2, w3);
                    fma2(acc[p][3][0], pa3, w0); fma2(acc[p][3][1], pa3, w1);
                    fma2(acc[p][3][2], pa3, w2); fma2(acc[p][3][3], pa3, w3);
                }
            }
            __syncthreads();
        }
#pragma unroll
        for (int p = 0; p < 2; p++) {
            const float* bias = p ? bv : bk;
            __half* C = p ? g_vatom : g_katom;
            float bb[8];
#pragma unroll
            for (int j = 0; j < 8; j++) bb[j] = bias[tx * 8 + j];
#pragma unroll
            for (int r = 0; r < 4; r++) {
                int gr = m0 + ty * 4 + r;
                if (gr >= NATOMS) continue;
#pragma unroll
                for (int j = 0; j < 4; j++) {
                    float lo, hi;
                    unpack2(acc[p][r][j], lo, hi);
                    *(__half2*)(C + (size_t)gr * 128 + tx * 8 + j * 2) =
                        __floats2half2_rn(lo + bb[j * 2], hi + bb[j * 2 + 1]);
                }
            }
        }
    } else {
        // q = S @ Wfq + bfq   (K = 256)
        const int m0 = (blockIdx.x - DUALB) * 64;
        ull acc[4][4];
#pragma unroll
        for (int r = 0; r < 4; r++)
#pragma unroll
            for (int j = 0; j < 4; j++) acc[r][j] = 0ull;

        for (int kc = 0; kc < 256; kc += 32) {
#pragma unroll
            for (int it = 0; it < 2; it++) {
                int lin = tid + 256 * it;
                int row = lin >> 3;
                int c4 = lin & 7;
                float4 v = make_float4(0.f, 0.f, 0.f, 0.f);
                int gr = m0 + row;
                if (gr < NB) v = *(const float4*)(g_S + (size_t)gr * 256 + kc + c4 * 4);
                As[c4 * 4 + 0][row] = v.x;
                As[c4 * 4 + 1][row] = v.y;
                As[c4 * 4 + 2][row] = v.z;
                As[c4 * 4 + 3][row] = v.w;
            }
#pragma unroll
            for (int it = 0; it < 4; it++) {
                int lin = tid + 256 * it;
                int row = lin >> 5;
                int c4 = lin & 31;
                *(float4*)&Ws[0][row][c4 * 4] =
                    *(const float4*)(g_Wfq + (size_t)(kc + row) * 128 + c4 * 4);
            }
            __syncthreads();
#pragma unroll
            for (int k = 0; k < 32; k++) {
                float a0 = As[k][ty * 4 + 0], a1 = As[k][ty * 4 + 1];
                float a2 = As[k][ty * 4 + 2], a3 = As[k][ty * 4 + 3];
                ull pa0 = pack2(a0, a0), pa1 = pack2(a1, a1);
                ull pa2 = pack2(a2, a2), pa3 = pack2(a3, a3);
                const ull* wp = (const ull*)&Ws[0][k][tx * 8];
                ull w0 = wp[0], w1 = wp[1], w2 = wp[2], w3 = wp[3];
                fma2(acc[0][0], pa0, w0); fma2(acc[0][1], pa0, w1);
                fma2(acc[0][2], pa0, w2); fma2(acc[0][3], pa0, w3);
                fma2(acc[1][0], pa1, w0); fma2(acc[1][1], pa1, w1);
                fma2(acc[1][2], pa1, w2); fma2(acc[1][3], pa1, w3);
                fma2(acc[2][0], pa2, w0); fma2(acc[2][1], pa2, w1);
                fma2(acc[2][2], pa2, w2); fma2(acc[2][3], pa2, w3);
                fma2(acc[3][0], pa3, w0); fma2(acc[3][1], pa3, w1);
                fma2(acc[3][2], pa3, w2); fma2(acc[3][3], pa3, w3);
            }
            __syncthreads();
        }
        float bb[8];
#pragma unroll
        for (int j = 0; j < 8; j++) bb[j] = g_bfq[tx * 8 + j];
#pragma unroll
        for (int r = 0; r < 4; r++) {
            int gr = m0 + ty * 4 + r;
            if (gr >= NB) continue;
#pragma unroll
            for (int j = 0; j < 4; j++) {
                float lo, hi;
                unpack2(acc[r][j], lo, hi);
                *(float2*)(g_q + (size_t)gr * 128 + tx * 8 + j * 2) =
                    make_float2(lo + bb[j * 2], hi + bb[j * 2 + 1]);
            }
        }
    }
}

// --------- per-bond gaussian-basis logit coefs: C[b][j][h] ----------------
// shuffle-free: lane owns (h = l>>2, j = (l&3)+4*jj); q in registers,
// Wk_bot via __ldg float4 (L1-hot across the 8 bonds per block).
__global__ __launch_bounds__(256) void qkcoef_kernel(const float* __restrict__ Wk) {
    int tid = threadIdx.x;
    int w = tid >> 5, l = tid & 31;
    int b = blockIdx.x * 8 + w;
    if (b >= NB) return;
    int h = l >> 2;
    int jg = l & 3;
    const float4* qp = (const float4*)&g_q[(size_t)b * 128 + h * 16];
    float4 q0 = qp[0], q1 = qp[1], q2 = qp[2], q3 = qp[3];
#pragma unroll
    for (int jj = 0; jj < 8; jj++) {
        int j = jg + 4 * jj;
        const float4* wp = (const float4*)&Wk[(size_t)(128 + j) * 128 + h * 16];
        float4 w0 = __ldg(wp + 0);
        float4 w1 = __ldg(wp + 1);
        float4 w2 = __ldg(wp + 2);
        float4 w3 = __ldg(wp + 3);
        float sum = q0.x * w0.x + q0.y * w0.y + q0.z * w0.z + q0.w * w0.w
                  + q1.x * w1.x + q1.y * w1.y + q1.z * w1.z + q1.w * w1.w
                  + q2.x * w2.x + q2.y * w2.y + q2.z * w2.z + q2.w * w2.w
                  + q3.x * w3.x + q3.y * w3.y + q3.z * w3.z + q3.w * w3.w;
        g_C[(size_t)b * 256 + j * 8 + h] = sum;
    }
}

// ------------- attention core (8 warps per bond, vcorr fused) --------------
__global__ __launch_bounds__(256) void attn_kernel(const float* __restrict__ Wv) {
    __shared__ float Cs[32][8];
    __shared__ float ssm[8][8];
    __shared__ float accs[8][128];
    __shared__ float sjs[8][256];
    __shared__ float sjtot[256];              // [h][j]
    __shared__ float Ssm[8];

    const int b = blockIdx.x;
    const int tid = threadIdx.x;
    const int w = tid >> 5;                   // 0..7
    const int l = tid & 31;
    const int h = l >> 2;
    const int t = l & 3;

    if (tid < 256) ((float*)Cs)[tid & 255] = g_C[(size_t)b * 256 + tid];
    __syncthreads();

    const float4 q4 = *(const float4*)&g_q[(size_t)b * 128 + l * 4];
    const int s0 = g_off[b], s1 = g_off[b + 1];

    float s = 0.f;
    float ax = 0.f, ay = 0.f, az = 0.f, aw = 0.f;
    float sj[8];
#pragma unroll
    for (int jj = 0; jj < 8; jj++) sj[jj] = 0.f;

    int i = s0 + w;
    float dist = 0.f;
    uint2 kraw = make_uint2(0u, 0u), vraw = make_uint2(0u, 0u);
    if (i < s1) {
        int src = g_src[i];
        dist = g_dist[i];
        kraw = *(const uint2*)&g_katom[(size_t)src * 128 + l * 4];
        vraw = *(const uint2*)&g_vatom[(size_t)src * 128 + l * 4];
    }
    while (i < s1) {
        int ni = i + 8;
        float ndist = 0.f;
        uint2 nkraw = make_uint2(0u, 0u), nvraw = make_uint2(0u, 0u);
        if (ni < s1) {
            int nsrc = g_src[ni];
            ndist = g_dist[ni];
            nkraw = *(const uint2*)&g_katom[(size_t)nsrc * 128 + l * 4];
            nvraw = *(const uint2*)&g_vatom[(size_t)nsrc * 128 + l * 4];
        }

        float2 k01 = __half22float2(*(__half2*)&kraw.x);
        float2 k23 = __half22float2(*(__half2*)&kraw.y);
        float2 v01 = __half22float2(*(__half2*)&vraw.x);
        float2 v23 = __half22float2(*(__half2*)&vraw.y);

        const bool hasg = dist < DCUT;           // warp-uniform branch
        float ev[8];
        float epart = 0.f;
        if (hasg) {
#pragma unroll
            for (int jj = 0; jj < 8; jj++) {
                int j = t + 4 * jj;
                float u = dist - (float)j * DELTA;
                float e = __expf(GCOEFF * u * u);
                ev[jj] = e;
                epart += e * Cs[j][h];
            }
        }
        float part = q4.x * k01.x + q4.y * k01.y + q4.z * k23.x + q4.w * k23.y + epart;
        part += __shfl_xor_sync(0xffffffffu, part, 1);
        part += __shfl_xor_sync(0xffffffffu, part, 2);
        float p = __expf(part * 0.25f);        // 1/sqrt(HEAD_DIM)

        s += p;
        ax += p * v01.x;
        ay += p * v01.y;
        az += p * v23.x;
        aw += p * v23.y;
        if (hasg) {
#pragma unroll
            for (int jj = 0; jj < 8; jj++) sj[jj] += p * ev[jj];
        }

        i = ni; dist = ndist; kraw = nkraw; vraw = nvraw;
    }

    if (t == 0) ssm[w][h] = s;
    accs[w][l * 4 + 0] = ax;
    accs[w][l * 4 + 1] = ay;
    accs[w][l * 4 + 2] = az;
    accs[w][l * 4 + 3] = aw;
#pragma unroll
    for (int jj = 0; jj < 8; jj++) sjs[w][l * 8 + jj] = sj[jj];
    __syncthreads();

    if (tid < 8) {
        float S = 0.f;
#pragma unroll
        for (int ww = 0; ww < 8; ww++) S += ssm[ww][tid];
        Ssm[tid] = S;
    }
    // reduce gaussian-basis accumulators into [h][j] layout (256 entries)
    {
        int idx = tid;
        int hh = idx >> 5, j = idx & 31;
        int tt2 = j & 3, jj = j >> 2;
        float v = 0.f;
#pragma unroll
        for (int ww = 0; ww < 8; ww++) v += sjs[ww][(4 * hh + tt2) * 8 + jj];
        sjtot[idx] = v;
    }
    __syncthreads();

    // fused vcorr: per-channel Wv_bot correction + normalization
    if (tid < 128) {
        const int c = tid;
        const int hh = c >> 4;
        float a = 0.f;
#pragma unroll
        for (int ww = 0; ww < 8; ww++) a += accs[ww][c];
        float corr = 0.f;
        const float* sjh = &sjtot[hh * 32];
#pragma unroll
        for (int j = 0; j < 32; j++)
            corr += __ldg(&Wv[(size_t)(128 + j) * 128 + c]) * sjh[j];
        g_msg[(size_t)b * 128 + c] = (a + corr) / (Ssm[hh] + 1e-16f);
    }
}

// ------- GELU GEMM + fused final projection: out = gelu(msg@Wo1+bo1)@Wt2+bt2
__global__ __launch_bounds__(256) void gemm_gelu_t2(const float* __restrict__ Wt2,
                                                    const float* __restrict__ bt2,
                                                    float* __restrict__ out) {
    __shared__ float As[32][65];
    __shared__ float Ws[32][128];
    const int tid = threadIdx.x;
    const int tx = tid & 15;
    const int ty = tid >> 4;
    const int m0 = blockIdx.x * 64;

    ull acc[4][4];
#pragma unroll
    for (int r = 0; r < 4; r++)
#pragma unroll
        for (int j = 0; j < 4; j++) acc[r][j] = 0ull;

    for (int kc = 0; kc < 128; kc += 32) {
#pragma unroll
        for (int it = 0; it < 2; it++) {
            int lin = tid + 256 * it;
            int row = lin >> 3;
            int c4 = lin & 7;
            float4 v = make_float4(0.f, 0.f, 0.f, 0.f);
            int gr = m0 + row;
            if (gr < NB) v = *(const float4*)(g_msg + (size_t)gr * 128 + kc + c4 * 4);
            As[c4 * 4 + 0][row] = v.x;
            As[c4 * 4 + 1][row] = v.y;
            As[c4 * 4 + 2][row] = v.z;
            As[c4 * 4 + 3][row] = v.w;
        }
#pragma unroll
        for (int it = 0; it < 4; it++) {
            int lin = tid + 256 * it;
            int row = lin >> 5;
            int c4 = lin & 31;
            *(float4*)&Ws[row][c4 * 4] =
                *(const float4*)(g_Wo1 + (size_t)(kc + row) * 128 + c4 * 4);
        }
        __syncthreads();
#pragma unroll
        for (int k = 0; k < 32; k++) {
            float a0 = As[k][ty * 4 + 0], a1 = As[k][ty * 4 + 1];
            float a2 = As[k][ty * 4 + 2], a3 = As[k][ty * 4 + 3];
            ull pa0 = pack2(a0, a0), pa1 = pack2(a1, a1);
            ull pa2 = pack2(a2, a2), pa3 = pack2(a3, a3);
            const ull* wp = (const ull*)&Ws[k][tx * 8];
            ull w0 = wp[0], w1 = wp[1], w2 = wp[2], w3 = wp[3];
            fma2(acc[0][0], pa0, w0); fma2(acc[0][1], pa0, w1);
            fma2(acc[0][2], pa0, w2); fma2(acc[0][3], pa0, w3);
            fma2(acc[1][0], pa1, w0); fma2(acc[1][1], pa1, w1);
            fma2(acc[1][2], pa1, w2); fma2(acc[1][3], pa1, w3);
            fma2(acc[2][0], pa2, w0); fma2(acc[2][1], pa2, w1);
            fma2(acc[2][2], pa2, w2); fma2(acc[2][3], pa2, w3);
            fma2(acc[3][0], pa3, w0); fma2(acc[3][1], pa3, w1);
            fma2(acc[3][2], pa3, w2); fma2(acc[3][3], pa3, w3);
        }
        __syncthreads();
    }

    float bb[8];
    float wt2a[8], wt2b[8];
#pragma unroll
    for (int j = 0; j < 8; j++) {
        bb[j] = g_bo1[tx * 8 + j];
        wt2a[j] = Wt2[(tx * 8 + j) * 2 + 0];
        wt2b[j] = Wt2[(tx * 8 + j) * 2 + 1];
    }
    float bt0 = bt2[0], bt1v = bt2[1];
#pragma unroll
    for (int r = 0; r < 4; r++) {
        int gr = m0 + ty * 4 + r;
        float a0 = 0.f, a1 = 0.f;
#pragma unroll
        for (int j = 0; j < 4; j++) {
            float lo, hi;
            unpack2(acc[r][j], lo, hi);
            lo += bb[j * 2];
            hi += bb[j * 2 + 1];
            lo = 0.5f * lo * (1.f + erff(lo * 0.70710678118654752f));
            hi = 0.5f * hi * (1.f + erff(hi * 0.70710678118654752f));
            a0 += lo * wt2a[j * 2] + hi * wt2a[j * 2 + 1];
            a1 += lo * wt2b[j * 2] + hi * wt2b[j * 2 + 1];
        }
#pragma unroll
        for (int o = 8; o; o >>= 1) {
            a0 += __shfl_xor_sync(0xffffffffu, a0, o);
            a1 += __shfl_xor_sync(0xffffffffu, a1, o);
        }
        if (tx == 0 && gr < NB) {
            out[gr * 2 + 0] = a0 + bt0;
            out[gr * 2 + 1] = a1 + bt1v;
        }
    }
}

// ------------------------- launch -----------------------------------------
extern "C" void kernel_launch(void* const* d_in, const int* in_sizes, int n_in,
                              void* d_out, int out_size) {
    const float* atom_feats = (const float*)d_in[0];
    const float* coords     = (const float*)d_in[1];
    const int*   rbi        = (const int*)d_in[2];
    const int*   etgt       = (const int*)d_in[3];
    const int*   esrc       = (const int*)d_in[4];
    const int*   tt         = (const int*)d_in[5];
    const float* W_dih      = (const float*)d_in[6];
    const float* b_dih      = (const float*)d_in[7];
    const float* Wq         = (const float*)d_in[8];
    const float* bq         = (const float*)d_in[9];
    const float* Wk         = (const float*)d_in[10];
    const float* bk         = (const float*)d_in[11];
    const float* Wv         = (const float*)d_in[12];
    const float* bv         = (const float*)d_in[13];
    const float* Wout       = (const float*)d_in[14];
    const float* bout       = (const float*)d_in[15];
    const float* Wt1        = (const float*)d_in[16];
    const float* bt1        = (const float*)d_in[17];
    const float* Wt2        = (const float*)d_in[18];
    const float* bt2        = (const float*)d_in[19];
    float* out = (float*)d_out;

    static cudaStream_t s1 = []() {
        cudaStream_t s;
        cudaStreamCreateWithFlags(&s, cudaStreamNonBlocking);
        return s;
    }();
    static cudaEvent_t evFork = []() {
        cudaEvent_t e;
        cudaEventCreateWithFlags(&e, cudaEventDisableTiming);
        return e;
    }();
    static cudaEvent_t evJoin = []() {
        cudaEvent_t e;
        cudaEventCreateWithFlags(&e, cudaEventDisableTiming);
        return e;
    }();

    void* pcnt;
    cudaGetSymbolAddress(&pcnt, g_cnt);

    // fork: stream B (s1) branches off the main stream
    cudaEventRecord(evFork, 0);
    cudaStreamWaitEvent(s1, evFork, 0);

    // ---- chain B (s1): gather_S + weight GEMMs -> big GEMMs -> qk coefs ----
    prep_kernel<<<5013, 256, 0, s1>>>(atom_feats, tt, W_dih, Wq, Wout, Wt1,
                                      b_dih, bq, bout, bt1);
    gemm_big<<<DUALB + QB, 256, 0, s1>>>(atom_feats, Wk, bk, Wv, bv);
    qkcoef_kernel<<<(NB + 7) / 8, 256, 0, s1>>>(Wk);

    // ---- chain A (stream 0): counting sort pipeline ----
    cudaMemsetAsync(pcnt, 0, NB * sizeof(int));
    rb_hist_kernel<<<1290, 256>>>(rbi, coords, etgt);
    scan_kernel<<<1, 1024>>>();
    scatter_kernel<<<(NE + 255) / 256, 256>>>(etgt);
    sortify_kernel<<<(NB + 7) / 8, 256>>>(esrc, coords);

    // join: main stream waits for chain B
    cudaEventRecord(evJoin, s1);
    cudaStreamWaitEvent(0, evJoin, 0);

    // ---- tail (stream 0): attn (8-warp, fused vcorr) -> gelu+t2 ----
    attn_kernel<<<NB, 256>>>(Wv);
    gemm_gelu_t2<<<(NB + 63) / 64, 256>>>(Wt2, bt2, out);

    (void)in_sizes; (void)n_in; (void)out_size;
}

// round 16
// speedup vs baseline: 1.1316x; 1.0761x over previous
#include <cuda_runtime.h>
#include <cuda_fp16.h>
#include <math.h>

// Problem constants (fixed shapes for this problem)
#define NATOMS 50000
#define NB     10000
#define NE     320000
#define MAXE   256
#define DD     32
#define DELTA  (5.0f / 31.0f)
#define GCOEFF (-0.5f / (DELTA * DELTA))
#define DCUT   6.0f

typedef unsigned long long ull;

// ------------------------- scratch (device globals; no allocs allowed) ----
__device__ float g_Wfq[256 * 128];            // (folded Wab) @ Wq
__device__ float g_bfq[128];
__device__ float g_Wo1[128 * 128];            // Wout @ Wt1
__device__ float g_bo1[128];
__device__ float g_S[NB * 256];               // [fi+fl | fj+fk]
__device__ float g_q[NB * 128];
__device__ float g_rbpos[NB * 3];
__device__ __half g_katom[NATOMS * 128];      // fp16 k (atom part, incl. bk)
__device__ __half g_vatom[NATOMS * 128];      // fp16 v (atom part, incl. bv)
__device__ float g_C[NB * 256];               // per-bond q·Wk_bot coefs [b][j][h]
__device__ float g_msg[NB * 128];
__device__ int   g_cnt[NB];
__device__ int   g_off[NB + 1];
__device__ int   g_cur[NB];
__device__ int   g_eidx[NE];
__device__ int   g_src[NE];                   // sorted edge src atoms
__device__ float g_dist[NE];                  // sorted edge distances

// ------------------------- f32x2 packed-FMA helpers -----------------------
__device__ __forceinline__ ull pack2(float x, float y) {
    ull r;
    asm("mov.b64 %0, {%1, %2};" : "=l"(r) : "f"(x), "f"(y));
    return r;
}
__device__ __forceinline__ void unpack2(ull v, float& lo, float& hi) {
    asm("mov.b64 {%0, %1}, %2;" : "=f"(lo), "=f"(hi) : "l"(v));
}
__device__ __forceinline__ void fma2(ull& d, ull a, ull b) {
    asm("fma.rn.f32x2 %0, %1, %2, %0;" : "+l"(d) : "l"(a), "l"(b));
}

// ------------------------- prep kernel (stream B) --------------------------
// blocks [0,5000): gather_S ; [5000,5012): weight GEMMs ; 5012: fused biases.
__global__ __launch_bounds__(256) void prep_kernel(const float* __restrict__ feats,
                                                   const int* __restrict__ tt,
                                                   const float* __restrict__ Wd,
                                                   const float* __restrict__ Wq,
                                                   const float* __restrict__ Wout,
                                                   const float* __restrict__ Wt1,
                                                   const float* __restrict__ b_dih,
                                                   const float* __restrict__ bq,
                                                   const float* __restrict__ bout,
                                                   const float* __restrict__ bt1) {
    __shared__ float As[32][33];
    __shared__ float Ws[32][128];
    int bid = blockIdx.x;
    int tid = threadIdx.x;
    if (bid < 5000) {
        int idx = bid * 256 + tid;               // < NB*128
        int b = idx >> 7, c = idx & 127;
        int ai = tt[b * 4 + 0], aj = tt[b * 4 + 1], ak = tt[b * 4 + 2], al = tt[b * 4 + 3];
        g_S[(size_t)b * 256 + c]       = feats[(size_t)ai * 128 + c] + feats[(size_t)al * 128 + c];
        g_S[(size_t)b * 256 + 128 + c] = feats[(size_t)aj * 128 + c] + feats[(size_t)ak * 128 + c];
        return;
    }
    if (bid == 5012) {
        if (tid < 128) {
            float s1 = 0.f, s2 = 0.f;
            for (int k = 0; k < 128; k++) {
                s1 += b_dih[k] * Wq[k * 128 + tid];
                s2 += bout[k] * Wt1[k * 128 + tid];
            }
            g_bfq[tid] = bq[tid] + 2.f * s1;
            g_bo1[tid] = bt1[tid] + s2;
        }
        return;
    }
    // weight GEMMs: Wfq = fold(W_dih)@Wq (8 blocks) ; Wo1 = Wout@Wt1 (4 blocks)
    const int wb = bid - 5000;
    const bool isFq = wb < 8;
    const int m0 = isFq ? wb * 32 : (wb - 8) * 32;
    const float* W = isFq ? Wq : Wt1;
    float* C = isFq ? g_Wfq : g_Wo1;
    const int tx = tid & 15;
    const int ty = tid >> 4;

    ull acc[2][4];
#pragma unroll
    for (int r = 0; r < 2; r++)
#pragma unroll
        for (int j = 0; j < 4; j++) acc[r][j] = 0ull;

    for (int kc = 0; kc < 128; kc += 32) {
        {
            int row = tid >> 3;
            int c4 = tid & 7;
            int gr = m0 + row;
            float4 v;
            if (isFq) {
                int o = (gr < 128) ? (gr + 384) : (gr + 128);
                float4 a = *(const float4*)(Wd + (size_t)gr * 128 + kc + c4 * 4);
                float4 b = *(const float4*)(Wd + (size_t)o * 128 + kc + c4 * 4);
                v = make_float4(a.x + b.x, a.y + b.y, a.z + b.z, a.w + b.w);
            } else {
                v = *(const float4*)(Wout + (size_t)gr * 128 + kc + c4 * 4);
            }
            As[c4 * 4 + 0][row] = v.x;
            As[c4 * 4 + 1][row] = v.y;
            As[c4 * 4 + 2][row] = v.z;
            As[c4 * 4 + 3][row] = v.w;
        }
#pragma unroll
        for (int it = 0; it < 4; it++) {
            int lin = tid + 256 * it;
            int row = lin >> 5;
            int c4 = lin & 31;
            *(float4*)&Ws[row][c4 * 4] =
                *(const float4*)(W + (size_t)(kc + row) * 128 + c4 * 4);
        }
        __syncthreads();
#pragma unroll
        for (int k = 0; k < 32; k++) {
            float a0 = As[k][ty * 2 + 0], a1 = As[k][ty * 2 + 1];
            ull pa0 = pack2(a0, a0), pa1 = pack2(a1, a1);
            const ull* wp = (const ull*)&Ws[k][tx * 8];
            ull w0 = wp[0], w1 = wp[1], w2 = wp[2], w3 = wp[3];
            fma2(acc[0][0], pa0, w0); fma2(acc[0][1], pa0, w1);
            fma2(acc[0][2], pa0, w2); fma2(acc[0][3], pa0, w3);
            fma2(acc[1][0], pa1, w0); fma2(acc[1][1], pa1, w1);
            fma2(acc[1][2], pa1, w2); fma2(acc[1][3], pa1, w3);
        }
        __syncthreads();
    }
#pragma unroll
    for (int r = 0; r < 2; r++) {
        int gr = m0 + ty * 2 + r;
#pragma unroll
        for (int j = 0; j < 4; j++) {
            float lo, hi;
            unpack2(acc[r][j], lo, hi);
            *(float2*)(C + (size_t)gr * 128 + tx * 8 + j * 2) = make_float2(lo, hi);
        }
    }
}

// ------------------- rbpos + histogram (stream A) ---------------------------
// blocks [0,40): rbpos ; [40,1290): hist.
__global__ __launch_bounds__(256) void rb_hist_kernel(const int* __restrict__ rbi,
                                                      const float* __restrict__ coords,
                                                      const int* __restrict__ etgt) {
    int bid = blockIdx.x;
    int tid = threadIdx.x;
    if (bid < 40) {
        int b = bid * 256 + tid;
        if (b < NB) {
            int a0 = rbi[b], a1 = rbi[NB + b];
#pragma unroll
            for (int i = 0; i < 3; i++)
                g_rbpos[b * 3 + i] = 0.5f * (coords[(size_t)a0 * 3 + i] + coords[(size_t)a1 * 3 + i]);
        }
    } else {
        int e = (bid - 40) * 256 + tid;
        if (e < NE) atomicAdd(&g_cnt[etgt[e]], 1);
    }
}

// ------------------------- counting-sort pipeline -------------------------
__global__ __launch_bounds__(1024) void scan_kernel() {
    __shared__ int sm[1024];
    int t = threadIdx.x;
    const int CH = 10;
    int base = t * CH;
    int loc[CH];
    int tot = 0;
#pragma unroll
    for (int i = 0; i < CH; i++) {
        int v = (base + i < NB) ? g_cnt[base + i] : 0;
        loc[i] = tot;
        tot += v;
    }
    sm[t] = tot;
    __syncthreads();
    for (int off = 1; off < 1024; off <<= 1) {
        int v = (t >= off) ? sm[t - off] : 0;
        __syncthreads();
        sm[t] += v;
        __syncthreads();
    }
    int excl = sm[t] - tot;
#pragma unroll
    for (int i = 0; i < CH; i++) {
        if (base + i < NB) {
            int o = excl + loc[i];
            g_off[base + i] = o;
            g_cur[base + i] = o;
        }
    }
    if (t == 1023) g_off[NB] = sm[1023];
}

__global__ void scatter_kernel(const int* __restrict__ etgt) {
    int e = blockIdx.x * blockDim.x + threadIdx.x;
    if (e < NE) {
        int p = atomicAdd(&g_cur[etgt[e]], 1);
        g_eidx[p] = e;
    }
}

// sort each bond's edge list (determinism), then emit src + dist per slot.
__global__ __launch_bounds__(256) void sortify_kernel(const int* __restrict__ esrc,
                                                      const float* __restrict__ coords) {
    __shared__ int buf[8][MAXE];
    int warp = threadIdx.x >> 5, lane = threadIdx.x & 31;
    int b = blockIdx.x * 8 + warp;
    if (b >= NB) return;
    int s = g_off[b], e = g_off[b + 1];
    int n = e - s;
    if (n <= 0) return;
    if (n <= MAXE) {
        for (int i = lane; i < n; i += 32) buf[warp][i] = g_eidx[s + i];
        __syncwarp();
        for (int i = lane; i < n; i += 32) {
            int v = buf[warp][i];
            int r = 0;
            for (int j = 0; j < n; j++) r += (buf[warp][j] < v);
            g_eidx[s + r] = v;
        }
        __syncwarp();
    } else {
        if (lane == 0) {
            for (int i = s + 1; i < e; i++) {
                int key = g_eidx[i];
                int j = i - 1;
                while (j >= s && g_eidx[j] > key) { g_eidx[j + 1] = g_eidx[j]; j--; }
                g_eidx[j + 1] = key;
            }
        }
        __syncwarp();
    }
    float rx = g_rbpos[b * 3 + 0];
    float ry = g_rbpos[b * 3 + 1];
    float rz = g_rbpos[b * 3 + 2];
    for (int i = lane; i < n; i += 32) {
        int ed = g_eidx[s + i];
        int src = esrc[ed];
        g_src[s + i] = src;
        float dx = coords[(size_t)src * 3 + 0] - rx;
        float dy = coords[(size_t)src * 3 + 1] - ry;
        float dz = coords[(size_t)src * 3 + 2] - rz;
        g_dist[s + i] = sqrtf(dx * dx + dy * dy + dz * dz);
    }
}

// ---------------- big GEMM launch: dual k/v (blocks < DUALB) + q ----------
#define DUALB 782
#define QB    157

__global__ __launch_bounds__(256) void gemm_big(const float* __restrict__ atom_feats,
                                                const float* __restrict__ Wk,
                                                const float* __restrict__ bk,
                                                const float* __restrict__ Wv,
                                                const float* __restrict__ bv) {
    __shared__ float As[32][65];
    __shared__ float Ws[2][32][128];
    const int tid = threadIdx.x;
    const int tx = tid & 15;
    const int ty = tid >> 4;

    if (blockIdx.x < DUALB) {
        const int m0 = blockIdx.x * 64;
        ull acc[2][4][4];
#pragma unroll
        for (int p = 0; p < 2; p++)
#pragma unroll
            for (int r = 0; r < 4; r++)
#pragma unroll
                for (int j = 0; j < 4; j++) acc[p][r][j] = 0ull;

        for (int kc = 0; kc < 128; kc += 32) {
#pragma unroll
            for (int it = 0; it < 2; it++) {
                int lin = tid + 256 * it;
                int row = lin >> 3;
                int c4 = lin & 7;
                float4 v = make_float4(0.f, 0.f, 0.f, 0.f);
                int gr = m0 + row;
                if (gr < NATOMS) v = *(const float4*)(atom_feats + (size_t)gr * 128 + kc + c4 * 4);
                As[c4 * 4 + 0][row] = v.x;
                As[c4 * 4 + 1][row] = v.y;
                As[c4 * 4 + 2][row] = v.z;
                As[c4 * 4 + 3][row] = v.w;
            }
#pragma unroll
            for (int it = 0; it < 4; it++) {
                int lin = tid + 256 * it;
                int row = lin >> 5;
                int c4 = lin & 31;
                *(float4*)&Ws[0][row][c4 * 4] =
                    *(const float4*)(Wk + (size_t)(kc + row) * 128 + c4 * 4);
                *(float4*)&Ws[1][row][c4 * 4] =
                    *(const float4*)(Wv + (size_t)(kc + row) * 128 + c4 * 4);
            }
            __syncthreads();
#pragma unroll
            for (int k = 0; k < 32; k++) {
                float a0 = As[k][ty * 4 + 0], a1 = As[k][ty * 4 + 1];
                float a2 = As[k][ty * 4 + 2], a3 = As[k][ty * 4 + 3];
                ull pa0 = pack2(a0, a0), pa1 = pack2(a1, a1);
                ull pa2 = pack2(a2, a2), pa3 = pack2(a3, a3);
#pragma unroll
                for (int p = 0; p < 2; p++) {
                    const ull* wp = (const ull*)&Ws[p][k][tx * 8];
                    ull w0 = wp[0], w1 = wp[1], w2 = wp[2], w3 = wp[3];
                    fma2(acc[p][0][0], pa0, w0); fma2(acc[p][0][1], pa0, w1);
                    fma2(acc[p][0][2], pa0, w2); fma2(acc[p][0][3], pa0, w3);
                    fma2(acc[p][1][0], pa1, w0); fma2(acc[p][1][1], pa1, w1);
                    fma2(acc[p][1][2], pa1, w2); fma2(acc[p][1][3], pa1, w3);
                    fma2(acc[p][2][0], pa2, w0); fma2(acc[p][2][1], pa2, w1);
                    fma2(acc[p][2][2], pa2, w2); fma2(acc[p][2][3], pa2, w3);
                    fma2(acc[p][3][0], pa3, w0); fma2(acc[p][3][1], pa3, w1);
                    fma2(acc[p][3][2], pa3, w2); fma2(acc[p][3][3], pa3, w3);
                }
            }
            __syncthreads();
        }
#pragma unroll
        for (int p = 0; p < 2; p++) {
            const float* bias = p ? bv : bk;
            __half* C = p ? g_vatom : g_katom;
            float bb[8];
#pragma unroll
            for (int j = 0; j < 8; j++) bb[j] = bias[tx * 8 + j];
#pragma unroll
            for (int r = 0; r < 4; r++) {
                int gr = m0 + ty * 4 + r;
                if (gr >= NATOMS) continue;
#pragma unroll
                for (int j = 0; j < 4; j++) {
                    float lo, hi;
                    unpack2(acc[p][r][j], lo, hi);
                    *(__half2*)(C + (size_t)gr * 128 + tx * 8 + j * 2) =
                        __floats2half2_rn(lo + bb[j * 2], hi + bb[j * 2 + 1]);
                }
            }
        }
    } else {
        // q = S @ Wfq + bfq   (K = 256)
        const int m0 = (blockIdx.x - DUALB) * 64;
        ull acc[4][4];
#pragma unroll
        for (int r = 0; r < 4; r++)
#pragma unroll
            for (int j = 0; j < 4; j++) acc[r][j] = 0ull;

        for (int kc = 0; kc < 256; kc += 32) {
#pragma unroll
            for (int it = 0; it < 2; it++) {
                int lin = tid + 256 * it;
                int row = lin >> 3;
                int c4 = lin & 7;
                float4 v = make_float4(0.f, 0.f, 0.f, 0.f);
                int gr = m0 + row;
                if (gr < NB) v = *(const float4*)(g_S + (size_t)gr * 256 + kc + c4 * 4);
                As[c4 * 4 + 0][row] = v.x;
                As[c4 * 4 + 1][row] = v.y;
                As[c4 * 4 + 2][row] = v.z;
                As[c4 * 4 + 3][row] = v.w;
            }
#pragma unroll
            for (int it = 0; it < 4; it++) {
                int lin = tid + 256 * it;
                int row = lin >> 5;
                int c4 = lin & 31;
                *(float4*)&Ws[0][row][c4 * 4] =
                    *(const float4*)(g_Wfq + (size_t)(kc + row) * 128 + c4 * 4);
            }
            __syncthreads();
#pragma unroll
            for (int k = 0; k < 32; k++) {
                float a0 = As[k][ty * 4 + 0], a1 = As[k][ty * 4 + 1];
                float a2 = As[k][ty * 4 + 2], a3 = As[k][ty * 4 + 3];
                ull pa0 = pack2(a0, a0), pa1 = pack2(a1, a1);
                ull pa2 = pack2(a2, a2), pa3 = pack2(a3, a3);
                const ull* wp = (const ull*)&Ws[0][k][tx * 8];
                ull w0 = wp[0], w1 = wp[1], w2 = wp[2], w3 = wp[3];
                fma2(acc[0][0], pa0, w0); fma2(acc[0][1], pa0, w1);
                fma2(acc[0][2], pa0, w2); fma2(acc[0][3], pa0, w3);
                fma2(acc[1][0], pa1, w0); fma2(acc[1][1], pa1, w1);
                fma2(acc[1][2], pa1, w2); fma2(acc[1][3], pa1, w3);
                fma2(acc[2][0], pa2, w0); fma2(acc[2][1], pa2, w1);
                fma2(acc[2][2], pa2, w2); fma2(acc[2][3], pa2, w3);
                fma2(acc[3][0], pa3, w0); fma2(acc[3][1], pa3, w1);
                fma2(acc[3][2], pa3, w2); fma2(acc[3][3], pa3, w3);
            }
            __syncthreads();
        }
        float bb[8];
#pragma unroll
        for (int j = 0; j < 8; j++) bb[j] = g_bfq[tx * 8 + j];
#pragma unroll
        for (int r = 0; r < 4; r++) {
            int gr = m0 + ty * 4 + r;
            if (gr >= NB) continue;
#pragma unroll
            for (int j = 0; j < 4; j++) {
                float lo, hi;
                unpack2(acc[r][j], lo, hi);
                *(float2*)(g_q + (size_t)gr * 128 + tx * 8 + j * 2) =
                    make_float2(lo + bb[j * 2], hi + bb[j * 2 + 1]);
            }
        }
    }
}

// --------- per-bond gaussian-basis logit coefs: C[b][j][h] ----------------
__global__ __launch_bounds__(256) void qkcoef_kernel(const float* __restrict__ Wk) {
    __shared__ float wkbs[32][128];
    int tid = threadIdx.x;
    for (int idx = tid; idx < 32 * 128; idx += 256) {
        int j = idx >> 7, c = idx & 127;
        wkbs[j][c] = Wk[(size_t)(128 + j) * 128 + c];
    }
    __syncthreads();
    int w = tid >> 5, l = tid & 31;
    int b = blockIdx.x * 8 + w;
    if (b >= NB) return;
    float4 q4 = *(const float4*)&g_q[(size_t)b * 128 + l * 4];
    int h = l >> 2;
#pragma unroll
    for (int j = 0; j < 32; j++) {
        float4 w4 = *(const float4*)&wkbs[j][l * 4];
        float part = q4.x * w4.x + q4.y * w4.y + q4.z * w4.z + q4.w * w4.w;
        part += __shfl_xor_sync(0xffffffffu, part, 1);
        part += __shfl_xor_sync(0xffffffffu, part, 2);
        if ((l & 3) == 0) g_C[(size_t)b * 256 + j * 8 + h] = part;
    }
}

// ------------------------- attention core (vcorr fused) --------------------
// block per bond, 4 warps split edges; fp16 k/v loads; epilogue applies the
// Wv_bot gaussian-basis correction + normalization and writes g_msg directly.
__global__ __launch_bounds__(128) void attn_kernel(const float* __restrict__ Wv) {
    __shared__ float Cs[32][8];
    __shared__ float ssm[4][8];
    __shared__ float accs[4][128];
    __shared__ float sjs[4][256];
    __shared__ float sjtot[256];              // [h][j]
    __shared__ float Ssm[8];

    const int b = blockIdx.x;
    const int tid = threadIdx.x;
    const int w = tid >> 5;
    const int l = tid & 31;
    const int h = l >> 2;
    const int t = l & 3;

    ((float*)Cs)[tid] = g_C[(size_t)b * 256 + tid];
    ((float*)Cs)[tid + 128] = g_C[(size_t)b * 256 + tid + 128];
    __syncthreads();

    const float4 q4 = *(const float4*)&g_q[(size_t)b * 128 + l * 4];
    const int s0 = g_off[b], s1 = g_off[b + 1];

    float s = 0.f;
    float ax = 0.f, ay = 0.f, az = 0.f, aw = 0.f;
    float sj[8];
#pragma unroll
    for (int jj = 0; jj < 8; jj++) sj[jj] = 0.f;

    int i = s0 + w;
    float dist = 0.f;
    uint2 kraw = make_uint2(0u, 0u), vraw = make_uint2(0u, 0u);
    if (i < s1) {
        int src = g_src[i];
        dist = g_dist[i];
        kraw = *(const uint2*)&g_katom[(size_t)src * 128 + l * 4];
        vraw = *(const uint2*)&g_vatom[(size_t)src * 128 + l * 4];
    }
    while (i < s1) {
        int ni = i + 4;
        float ndist = 0.f;
        uint2 nkraw = make_uint2(0u, 0u), nvraw = make_uint2(0u, 0u);
        if (ni < s1) {
            int nsrc = g_src[ni];
            ndist = g_dist[ni];
            nkraw = *(const uint2*)&g_katom[(size_t)nsrc * 128 + l * 4];
            nvraw = *(const uint2*)&g_vatom[(size_t)nsrc * 128 + l * 4];
        }

        float2 k01 = __half22float2(*(__half2*)&kraw.x);
        float2 k23 = __half22float2(*(__half2*)&kraw.y);
        float2 v01 = __half22float2(*(__half2*)&vraw.x);
        float2 v23 = __half22float2(*(__half2*)&vraw.y);

        const bool hasg = dist < DCUT;           // warp-uniform branch
        float ev[8];
        float epart = 0.f;
        if (hasg) {
#pragma unroll
            for (int jj = 0; jj < 8; jj++) {
                int j = t + 4 * jj;
                float u = dist - (float)j * DELTA;
                float e = __expf(GCOEFF * u * u);
                ev[jj] = e;
                epart += e * Cs[j][h];
            }
        }
        float part = q4.x * k01.x + q4.y * k01.y + q4.z * k23.x + q4.w * k23.y + epart;
        part += __shfl_xor_sync(0xffffffffu, part, 1);
        part += __shfl_xor_sync(0xffffffffu, part, 2);
        float p = __expf(part * 0.25f);        // 1/sqrt(HEAD_DIM)

        s += p;
        ax += p * v01.x;
        ay += p * v01.y;
        az += p * v23.x;
        aw += p * v23.y;
        if (hasg) {
#pragma unroll
            for (int jj = 0; jj < 8; jj++) sj[jj] += p * ev[jj];
        }

        i = ni; dist = ndist; kraw = nkraw; vraw = nvraw;
    }

    if (t == 0) { ssm[w][h] = s; }
    accs[w][l * 4 + 0] = ax;
    accs[w][l * 4 + 1] = ay;
    accs[w][l * 4 + 2] = az;
    accs[w][l * 4 + 3] = aw;
#pragma unroll
    for (int jj = 0; jj < 8; jj++) sjs[w][l * 8 + jj] = sj[jj];
    __syncthreads();

    if (tid < 8) {
        float S = 0.f;
#pragma unroll
        for (int ww = 0; ww < 4; ww++) S += ssm[ww][tid];
        Ssm[tid] = S;
    }
    // reduce gaussian-basis accumulators into [h][j] layout
#pragma unroll
    for (int r = 0; r < 2; r++) {
        int idx = tid + 128 * r;
        int hh = idx >> 5, j = idx & 31;
        int tt2 = j & 3, jj = j >> 2;
        float v = 0.f;
#pragma unroll
        for (int ww = 0; ww < 4; ww++) v += sjs[ww][(4 * hh + tt2) * 8 + jj];
        sjtot[idx] = v;
    }
    __syncthreads();

    // fused vcorr: per-channel Wv_bot correction + normalization
    {
        const int c = tid;
        const int hh = c >> 4;
        float a = accs[0][c] + accs[1][c] + accs[2][c] + accs[3][c];
        float corr = 0.f;
        const float* sjh = &sjtot[hh * 32];
#pragma unroll
        for (int j = 0; j < 32; j++)
            corr += __ldg(&Wv[(size_t)(128 + j) * 128 + c]) * sjh[j];
        g_msg[(size_t)b * 128 + c] = (a + corr) / (Ssm[hh] + 1e-16f);
    }
}

// ------- GELU GEMM + fused final projection: out = gelu(msg@Wo1+bo1)@Wt2+bt2
__global__ __launch_bounds__(256) void gemm_gelu_t2(const float* __restrict__ Wt2,
                                                    const float* __restrict__ bt2,
                                                    float* __restrict__ out) {
    __shared__ float As[32][65];
    __shared__ float Ws[32][128];
    const int tid = threadIdx.x;
    const int tx = tid & 15;
    const int ty = tid >> 4;
    const int m0 = blockIdx.x * 64;

    ull acc[4][4];
#pragma unroll
    for (int r = 0; r < 4; r++)
#pragma unroll
        for (int j = 0; j < 4; j++) acc[r][j] = 0ull;

    for (int kc = 0; kc < 128; kc += 32) {
#pragma unroll
        for (int it = 0; it < 2; it++) {
            int lin = tid + 256 * it;
            int row = lin >> 3;
            int c4 = lin & 7;
            float4 v = make_float4(0.f, 0.f, 0.f, 0.f);
            int gr = m0 + row;
            if (gr < NB) v = *(const float4*)(g_msg + (size_t)gr * 128 + kc + c4 * 4);
            As[c4 * 4 + 0][row] = v.x;
            As[c4 * 4 + 1][row] = v.y;
            As[c4 * 4 + 2][row] = v.z;
            As[c4 * 4 + 3][row] = v.w;
        }
#pragma unroll
        for (int it = 0; it < 4; it++) {
            int lin = tid + 256 * it;
            int row = lin >> 5;
            int c4 = lin & 31;
            *(float4*)&Ws[row][c4 * 4] =
                *(const float4*)(g_Wo1 + (size_t)(kc + row) * 128 + c4 * 4);
        }
        __syncthreads();
#pragma unroll
        for (int k = 0; k < 32; k++) {
            float a0 = As[k][ty * 4 + 0], a1 = As[k][ty * 4 + 1];
            float a2 = As[k][ty * 4 + 2], a3 = As[k][ty * 4 + 3];
            ull pa0 = pack2(a0, a0), pa1 = pack2(a1, a1);
            ull pa2 = pack2(a2, a2), pa3 = pack2(a3, a3);
            const ull* wp = (const ull*)&Ws[k][tx * 8];
            ull w0 = wp[0], w1 = wp[1], w2 = wp[2], w3 = wp[3];
            fma2(acc[0][0], pa0, w0); fma2(acc[0][1], pa0, w1);
            fma2(acc[0][2], pa0, w2); fma2(acc[0][3], pa0, w3);
            fma2(acc[1][0], pa1, w0); fma2(acc[1][1], pa1, w1);
            fma2(acc[1][2], pa1, w2); fma2(acc[1][3], pa1, w3);
            fma2(acc[2][0], pa2, w0); fma2(acc[2][1], pa2, w1);
            fma2(acc[2][2], pa2, w2); fma2(acc[2][3], pa2, w3);
            fma2(acc[3][0], pa3, w0); fma2(acc[3][1], pa3, w1);
            fma2(acc[3][2], pa3, w2); fma2(acc[3][3], pa3, w3);
        }
        __syncthreads();
    }

    float bb[8];
    float wt2a[8], wt2b[8];
#pragma unroll
    for (int j = 0; j < 8; j++) {
        bb[j] = g_bo1[tx * 8 + j];
        wt2a[j] = Wt2[(tx * 8 + j) * 2 + 0];
        wt2b[j] = Wt2[(tx * 8 + j) * 2 + 1];
    }
    float bt0 = bt2[0], bt1v = bt2[1];
#pragma unroll
    for (int r = 0; r < 4; r++) {
        int gr = m0 + ty * 4 + r;
        float a0 = 0.f, a1 = 0.f;
#pragma unroll
        for (int j = 0; j < 4; j++) {
            float lo, hi;
            unpack2(acc[r][j], lo, hi);
            lo += bb[j * 2];
            hi += bb[j * 2 + 1];
            lo = 0.5f * lo * (1.f + erff(lo * 0.70710678118654752f));
            hi = 0.5f * hi * (1.f + erff(hi * 0.70710678118654752f));
            a0 += lo * wt2a[j * 2] + hi * wt2a[j * 2 + 1];
            a1 += lo * wt2b[j * 2] + hi * wt2b[j * 2 + 1];
        }
#pragma unroll
        for (int o = 8; o; o >>= 1) {
            a0 += __shfl_xor_sync(0xffffffffu, a0, o);
            a1 += __shfl_xor_sync(0xffffffffu, a1, o);
        }
        if (tx == 0 && gr < NB) {
            out[gr * 2 + 0] = a0 + bt0;
            out[gr * 2 + 1] = a1 + bt1v;
        }
    }
}

// ------------------------- launch -----------------------------------------
extern "C" void kernel_launch(void* const* d_in, const int* in_sizes, int n_in,
                              void* d_out, int out_size) {
    const float* atom_feats = (const float*)d_in[0];
    const float* coords     = (const float*)d_in[1];
    const int*   rbi        = (const int*)d_in[2];
    const int*   etgt       = (const int*)d_in[3];
    const int*   esrc       = (const int*)d_in[4];
    const int*   tt         = (const int*)d_in[5];
    const float* W_dih      = (const float*)d_in[6];
    const float* b_dih      = (const float*)d_in[7];
    const float* Wq         = (const float*)d_in[8];
    const float* bq         = (const float*)d_in[9];
    const float* Wk         = (const float*)d_in[10];
    const float* bk         = (const float*)d_in[11];
    const float* Wv         = (const float*)d_in[12];
    const float* bv         = (const float*)d_in[13];
    const float* Wout       = (const float*)d_in[14];
    const float* bout       = (const float*)d_in[15];
    const float* Wt1        = (const float*)d_in[16];
    const float* bt1        = (const float*)d_in[17];
    const float* Wt2        = (const float*)d_in[18];
    const float* bt2        = (const float*)d_in[19];
    float* out = (float*)d_out;

    static cudaStream_t s1 = []() {
        cudaStream_t s;
        cudaStreamCreateWithFlags(&s, cudaStreamNonBlocking);
        return s;
    }();
    static cudaEvent_t evFork = []() {
        cudaEvent_t e;
        cudaEventCreateWithFlags(&e, cudaEventDisableTiming);
        return e;
    }();
    static cudaEvent_t evJoin = []() {
        cudaEvent_t e;
        cudaEventCreateWithFlags(&e, cudaEventDisableTiming);
        return e;
    }();

    void* pcnt;
    cudaGetSymbolAddress(&pcnt, g_cnt);

    // fork: stream B (s1) branches off the main stream
    cudaEventRecord(evFork, 0);
    cudaStreamWaitEvent(s1, evFork, 0);

    // ---- chain B (s1): gather_S + weight GEMMs -> big GEMMs -> qk coefs ----
    prep_kernel<<<5013, 256, 0, s1>>>(atom_feats, tt, W_dih, Wq, Wout, Wt1,
                                      b_dih, bq, bout, bt1);
    gemm_big<<<DUALB + QB, 256, 0, s1>>>(atom_feats, Wk, bk, Wv, bv);
    qkcoef_kernel<<<(NB + 7) / 8, 256, 0, s1>>>(Wk);

    // ---- chain A (stream 0): counting sort pipeline ----
    cudaMemsetAsync(pcnt, 0, NB * sizeof(int));
    rb_hist_kernel<<<1290, 256>>>(rbi, coords, etgt);
    scan_kernel<<<1, 1024>>>();
    scatter_kernel<<<(NE + 255) / 256, 256>>>(etgt);
    sortify_kernel<<<(NB + 7) / 8, 256>>>(esrc, coords);

    // join: main stream waits for chain B
    cudaEventRecord(evJoin, s1);
    cudaStreamWaitEvent(0, evJoin, 0);

    // ---- tail (stream 0): attn (with fused vcorr) -> gelu+t2 ----
    attn_kernel<<<NB, 128>>>(Wv);
    gemm_gelu_t2<<<(NB + 63) / 64, 256>>>(Wt2, bt2, out);

    (void)in_sizes; (void)n_in; (void)out_size;
}